// round 11
// baseline (speedup 1.0000x reference)
#include <cuda_runtime.h>
#include <cuda_fp16.h>
#include <cstdint>

#define NETS 500
#define DIMS 10
#define NBATCH 32
#define TSTEPS 8
#define NSAMP 256            // s = t*32 + n
#define H1DIM 300
#define AIN_R 5000
#define ANET_R 250000
#define KDIM 500
#define KPAD 512

// ---------------- scratch ----------------
__device__ float d_h2[NSAMP * H1DIM];
__device__ __half d_g2h[NSAMP * KPAD];              // fp16 g2, zero-padded to 512
__device__ float d_a_in[(size_t)NSAMP * AIN_R];
__device__ float d_a_raw[(size_t)NSAMP * ANET_R];   // 256 MB
__device__ unsigned d_mm[4 * TSTEPS];
__device__ float d_xb[NSAMP * NETS];
__device__ float d_s1[NSAMP * NETS];
__device__ float d_s2[NSAMP * NETS];

// ---------------- helpers ----------------
__device__ __forceinline__ uint32_t smem_u32(const void* p) {
  uint32_t a;
  asm("{ .reg .u64 t; cvta.to.shared.u64 t, %1; cvt.u32.u64 %0, t; }" : "=r"(a) : "l"(p));
  return a;
}
__device__ __forceinline__ float wredsum(float v) {
#pragma unroll
  for (int o = 16; o > 0; o >>= 1) v += __shfl_xor_sync(0xffffffffu, v, o);
  return v;
}
__device__ __forceinline__ float sigmoid_t(float z) {
  float t;
  asm("tanh.approx.f32 %0, %1;" : "=f"(t) : "f"(0.5f * z));
  return fmaf(0.5f, t, 0.5f);
}
__device__ __forceinline__ void ldsm4(unsigned* r, uint32_t addr) {
  asm volatile("ldmatrix.sync.aligned.m8n8.x4.shared.b16 {%0,%1,%2,%3}, [%4];"
               : "=r"(r[0]), "=r"(r[1]), "=r"(r[2]), "=r"(r[3]) : "r"(addr));
}
__device__ __forceinline__ void mma_f16(float* c, const unsigned* a, const unsigned* b) {
  asm volatile(
      "mma.sync.aligned.m16n8k16.row.col.f32.f16.f16.f32 "
      "{%0,%1,%2,%3}, {%4,%5,%6,%7}, {%8,%9}, {%0,%1,%2,%3};"
      : "+f"(c[0]), "+f"(c[1]), "+f"(c[2]), "+f"(c[3])
      : "r"(a[0]), "r"(a[1]), "r"(a[2]), "r"(a[3]), "r"(b[0]), "r"(b[1]));
}
__device__ __forceinline__ void cp_async16(uint32_t dst, const void* src) {
  asm volatile("cp.async.ca.shared.global [%0], [%1], 16;" :: "r"(dst), "l"(src));
}
#define CP_COMMIT() asm volatile("cp.async.commit_group;" ::: "memory")
#define CP_WAIT0()  asm volatile("cp.async.wait_group 0;" ::: "memory")

// ---------------- small MLPs (+ d_mm init, g2 -> fp16) ----------------
__global__ __launch_bounds__(256) void k_mlp(
    const float* __restrict__ x,
    const float* __restrict__ W1, const float* __restrict__ b1,
    const float* __restrict__ W2, const float* __restrict__ b2,
    const float* __restrict__ Wn1, const float* __restrict__ bn1,
    const float* __restrict__ Wn2, const float* __restrict__ bn2) {
  __shared__ float uu[DIMS], h1s[H1DIM], g1s[NETS];
  int s = blockIdx.x, tid = threadIdx.x;
  int n = s & 31, t = s >> 5;
  if (s == 0 && tid < TSTEPS) {
    d_mm[0 * TSTEPS + tid] = 0x7F800000u; d_mm[1 * TSTEPS + tid] = 0u;
    d_mm[2 * TSTEPS + tid] = 0x7F800000u; d_mm[3 * TSTEPS + tid] = 0u;
  }
  if (tid < DIMS) uu[tid] = x[n * (DIMS * TSTEPS) + tid * TSTEPS + t];
  if (tid < KPAD - NETS) d_g2h[s * KPAD + NETS + tid] = __ushort_as_half(0);
  __syncthreads();
  for (int o = tid; o < H1DIM; o += 256) {
    float a = b1[o];
#pragma unroll
    for (int k = 0; k < DIMS; k++) a = fmaf(W1[o * DIMS + k], uu[k], a);
    h1s[o] = fmaxf(a, 0.f);
  }
  for (int o = tid; o < NETS; o += 256) {
    float a = bn1[o];
#pragma unroll
    for (int k = 0; k < DIMS; k++) a = fmaf(Wn1[o * DIMS + k], uu[k], a);
    g1s[o] = fmaxf(a, 0.f);
  }
  __syncthreads();
  int w = tid >> 5, lane = tid & 31;
  for (int o = w; o < H1DIM; o += 8) {
    float a = 0.f;
    for (int k = lane; k < H1DIM; k += 32) a = fmaf(W2[o * H1DIM + k], h1s[k], a);
    a = wredsum(a);
    if (lane == 0) d_h2[s * H1DIM + o] = fmaxf(a + b2[o], 0.f);
  }
  for (int o = w; o < NETS; o += 8) {
    float a = 0.f;
    for (int k = lane; k < NETS; k += 32) a = fmaf(Wn2[o * NETS + k], g1s[k], a);
    a = wredsum(a);
    if (lane == 0) d_g2h[s * KPAD + o] = __float2half_rn(fmaxf(a + bn2[o], 0.f));
  }
}

// ================= fused GEMM kernel =================
// Single-pass fp16 GEMM: A = fp16(Wn3), B = fp16(g2), fp32 accum.
// CTA tile M=128 x N=256, K-chunk 64 (8 iterations), 1 CTA/SM.
// SMEM row = 64 halfs (128B) + 16B pad = 144B.
#define A_ROWB 144u
#define A_BLK  (128u * 144u)    // 18432
#define B_BLK  (256u * 144u)    // 36864
#define B_OFF  A_BLK            // 18432
#define BUFSZ  (B_OFF + B_BLK)  // 55296
#define SMEM_BIG (2u * BUFSZ + 64u)  // 110656
#define NCHUNK 8
#define NBIG  ((ANET_R + 127) / 128)   // 1954
#define NGEMM (TSTEPS * ((AIN_R + 127) / 128))  // 320

__device__ __forceinline__ void bigmm_body(
    char* smem, uint32_t sb,
    const float* __restrict__ W, const float* __restrict__ bias,
    float* __restrict__ outp, unsigned* __restrict__ mm) {
  int tid = threadIdx.x, wid = tid >> 5, lane = tid & 31;
  int r0 = blockIdx.x * 128;

  float acc[2][16][4];
#pragma unroll
  for (int a = 0; a < 2; a++)
#pragma unroll
    for (int b = 0; b < 16; b++)
#pragma unroll
      for (int c = 0; c < 4; c++) acc[a][b][c] = 0.f;

  unsigned warpM0 = (wid & 3) * 32, warpN0 = (wid >> 2) * 128;
  unsigned a_off_lane = ((lane & 7) + ((lane >> 3) & 1) * 8) * A_ROWB + (lane >> 4) * 16;
  unsigned b_off_lane = ((lane & 7) + (lane >> 4) * 8) * A_ROWB + ((lane >> 3) & 1) * 16;

  float2 areg[8];
  const unsigned* g2w = (const unsigned*)d_g2h;

  // A: 128 rows x 64 fp32 per chunk = 4096 float2; 16/thread, in 2 halves of 8
  auto ldA = [&](int ch, int half) {
    int k0 = ch * 64;
#pragma unroll
    for (int i = 0; i < 8; i++) {
      int idx = tid + (half * 8 + i) * 256;
      int row = idx >> 5, kp = idx & 31;
      int rg = r0 + row, kg = k0 + 2 * kp;
      bool val = (rg < ANET_R) && (kg + 1 < KDIM);
      areg[i] = val ? *(const float2*)(W + (size_t)rg * KDIM + kg) : make_float2(0.f, 0.f);
    }
  };
  auto stsA = [&](int buf, int half) {
#pragma unroll
    for (int i = 0; i < 8; i++) {
      int idx = tid + (half * 8 + i) * 256;
      int row = idx >> 5, kp = idx & 31;
      __half2 h = __float22half2_rn(areg[i]);
      unsigned off = (unsigned)buf * BUFSZ + (unsigned)row * A_ROWB + (unsigned)kp * 4;
      *(unsigned*)(smem + off) = *(unsigned*)&h;
    }
  };
  // B: 256 rows x 128B per chunk; 8 x 16B per thread
  auto cpB = [&](int ch, int buf) {
    int k0w = ch * 32;
#pragma unroll
    for (int i = 0; i < 8; i++) {
      int idx = tid + i * 256;
      int s = idx >> 3, gran = idx & 7;
      unsigned dst = sb + (unsigned)buf * BUFSZ + B_OFF +
                     (unsigned)s * A_ROWB + (unsigned)gran * 16;
      cp_async16(dst, (const void*)(g2w + (size_t)s * (KPAD / 2) + k0w + gran * 4));
    }
  };
  auto mmaHalf = [&](int buf, int kshalf) {
    unsigned base = sb + (unsigned)buf * BUFSZ;
#pragma unroll
    for (int ks = kshalf * 2; ks < kshalf * 2 + 2; ks++) {
      unsigned koff = (unsigned)ks * 32;
      unsigned Ah[2][4];
#pragma unroll
      for (int mt = 0; mt < 2; mt++) {
        unsigned aaddr = base + (warpM0 + mt * 16) * A_ROWB + a_off_lane + koff;
        ldsm4(Ah[mt], aaddr);
      }
#pragma unroll
      for (int ntp = 0; ntp < 8; ntp++) {
        unsigned baddr = base + B_OFF + (warpN0 + ntp * 16) * A_ROWB + b_off_lane + koff;
        unsigned Bh[4];
        ldsm4(Bh, baddr);
#pragma unroll
        for (int mt = 0; mt < 2; mt++) {
          mma_f16(acc[mt][2 * ntp], Ah[mt], Bh);
          mma_f16(acc[mt][2 * ntp + 1], Ah[mt], Bh + 2);
        }
      }
    }
  };

  // prologue: fill buffer 0
  ldA(0, 0); stsA(0, 0); ldA(0, 1); stsA(0, 1);
  cpB(0, 0); CP_COMMIT();
  CP_WAIT0();
  __syncthreads();

  int buf = 0;
#pragma unroll 1
  for (int ch = 0; ch < NCHUNK; ch++) {
    if (ch < NCHUNK - 1) { ldA(ch + 1, 0); cpB(ch + 1, buf ^ 1); CP_COMMIT(); }
    mmaHalf(buf, 0);
    if (ch < NCHUNK - 1) { stsA(buf ^ 1, 0); ldA(ch + 1, 1); }
    mmaHalf(buf, 1);
    if (ch < NCHUNK - 1) { stsA(buf ^ 1, 1); CP_WAIT0(); }
    __syncthreads();
    buf ^= 1;
  }

  // ---- epilogue: bias + relu + store + per-t min/max ----
  unsigned* smm = (unsigned*)(smem + 2u * BUFSZ);
  if (tid < 8) { smm[tid] = 0x7F800000u; smm[tid + 8] = 0u; }
  __syncthreads();

  float lmn[4], lmx[4];
#pragma unroll
  for (int tg = 0; tg < 4; tg++) { lmn[tg] = __int_as_float(0x7F800000); lmx[tg] = 0.f; }

#pragma unroll
  for (int mt = 0; mt < 2; mt++) {
    int rA = r0 + (int)warpM0 + mt * 16 + (lane >> 2);
    int rB = rA + 8;
    float bA = (rA < ANET_R) ? bias[rA] : 0.f;
    float bB = (rB < ANET_R) ? bias[rB] : 0.f;
#pragma unroll
    for (int nt = 0; nt < 16; nt++) {
      int n0 = (int)warpN0 + nt * 8 + (lane & 3) * 2;
      int tg = nt >> 2;
      float v0 = fmaxf(acc[mt][nt][0] + bA, 0.f);
      float v1 = fmaxf(acc[mt][nt][1] + bA, 0.f);
      float v2 = fmaxf(acc[mt][nt][2] + bB, 0.f);
      float v3 = fmaxf(acc[mt][nt][3] + bB, 0.f);
      if (rA < ANET_R) {
        outp[(size_t)n0 * ANET_R + rA] = v0;
        outp[(size_t)(n0 + 1) * ANET_R + rA] = v1;
        lmn[tg] = fminf(lmn[tg], fminf(v0, v1));
        lmx[tg] = fmaxf(lmx[tg], fmaxf(v0, v1));
      }
      if (rB < ANET_R) {
        outp[(size_t)n0 * ANET_R + rB] = v2;
        outp[(size_t)(n0 + 1) * ANET_R + rB] = v3;
        lmn[tg] = fminf(lmn[tg], fminf(v2, v3));
        lmx[tg] = fmaxf(lmx[tg], fmaxf(v2, v3));
      }
    }
  }
#pragma unroll
  for (int tg = 0; tg < 4; tg++) {
    float mn = lmn[tg], mx = lmx[tg];
#pragma unroll
    for (int o = 16; o > 0; o >>= 1) {
      mn = fminf(mn, __shfl_xor_sync(0xffffffffu, mn, o));
      mx = fmaxf(mx, __shfl_xor_sync(0xffffffffu, mx, o));
    }
    if (lane == 0) {
      int tglob = (int)(warpN0 >> 5) + tg;
      atomicMin(&smm[tglob], __float_as_uint(mn));
      atomicMax(&smm[8 + tglob], __float_as_uint(mx));
    }
  }
  __syncthreads();
  if (tid < 8) {
    atomicMin(&mm[2 * TSTEPS + tid], smm[tid]);
    atomicMax(&mm[3 * TSTEPS + tid], smm[tid + 8]);
  }
}

__device__ __forceinline__ void ain_gemm_body(
    char* smem, int gb,
    const float* __restrict__ G, const float* __restrict__ W,
    const float* __restrict__ bias, float* __restrict__ out,
    unsigned* __restrict__ mmin, unsigned* __restrict__ mmax) {
  const int R = AIN_R, K = H1DIM;
  float (*Wsh)[132] = (float(*)[132])smem;
  float (*Gsh)[34]  = (float(*)[34])(smem + 16 * 132 * 4);
  float* rminmax = (float*)(smem + 16 * 132 * 4 + 16 * 34 * 4);

  int sblk = gb & 7, rblk = gb >> 3, tid = threadIdx.x;
  int rg = tid & 15, sg = tid >> 4;
  int r0 = rblk * 128, s0 = sblk * 32;
  float acc[8][2];
#pragma unroll
  for (int i = 0; i < 8; i++) { acc[i][0] = 0.f; acc[i][1] = 0.f; }
  for (int k0 = 0; k0 < K; k0 += 16) {
#pragma unroll
    for (int i = 0; i < 8; i++) {
      int idx = tid + i * 256, rr = idx >> 4, kk = idx & 15;
      int gr = r0 + rr, gk = k0 + kk;
      Wsh[kk][rr] = (gr < R && gk < K) ? W[(size_t)gr * K + gk] : 0.f;
    }
#pragma unroll
    for (int i = 0; i < 2; i++) {
      int idx = tid + i * 256, ss = idx >> 4, kk = idx & 15;
      int gk = k0 + kk;
      Gsh[kk][ss] = (gk < K) ? G[(size_t)(s0 + ss) * K + gk] : 0.f;
    }
    __syncthreads();
#pragma unroll
    for (int k = 0; k < 16; k++) {
      float4 w0 = *(const float4*)&Wsh[k][rg * 4];
      float4 w1 = *(const float4*)&Wsh[k][64 + rg * 4];
      float g0 = Gsh[k][sg * 2], g1 = Gsh[k][sg * 2 + 1];
      float wv[8] = {w0.x, w0.y, w0.z, w0.w, w1.x, w1.y, w1.z, w1.w};
#pragma unroll
      for (int i = 0; i < 8; i++) {
        acc[i][0] = fmaf(wv[i], g0, acc[i][0]);
        acc[i][1] = fmaf(wv[i], g1, acc[i][1]);
      }
    }
    __syncthreads();
  }
  float tmin = __int_as_float(0x7F800000), tmax = 0.f;
#pragma unroll
  for (int i = 0; i < 8; i++) {
    int r = r0 + ((i < 4) ? (rg * 4 + i) : (64 + rg * 4 + i - 4));
    if (r < R) {
      float b = bias[r];
#pragma unroll
      for (int j = 0; j < 2; j++) {
        float v = fmaxf(acc[i][j] + b, 0.f);
        out[(size_t)(s0 + sg * 2 + j) * R + r] = v;
        tmin = fminf(tmin, v); tmax = fmaxf(tmax, v);
      }
    }
  }
#pragma unroll
  for (int o = 16; o > 0; o >>= 1) {
    tmin = fminf(tmin, __shfl_xor_sync(0xffffffffu, tmin, o));
    tmax = fmaxf(tmax, __shfl_xor_sync(0xffffffffu, tmax, o));
  }
  int w = tid >> 5, lane = tid & 31;
  if (lane == 0) { rminmax[w] = tmin; rminmax[8 + w] = tmax; }
  __syncthreads();
  if (tid == 0) {
#pragma unroll
    for (int i = 1; i < 8; i++) {
      tmin = fminf(tmin, rminmax[i]); tmax = fmaxf(tmax, rminmax[8 + i]);
    }
    atomicMin(&mmin[sblk], __float_as_uint(tmin));
    atomicMax(&mmax[sblk], __float_as_uint(tmax));
  }
}

__global__ __launch_bounds__(256, 1) void k_fused(
    const float* __restrict__ Wn3, const float* __restrict__ bn3,
    const float* __restrict__ W3, const float* __restrict__ b3,
    float* __restrict__ a_raw, float* __restrict__ a_in,
    unsigned* __restrict__ mm) {
  extern __shared__ char smem[];
  uint32_t sb = smem_u32(smem);
  if (blockIdx.x < NBIG) {
    bigmm_body(smem, sb, Wn3, bn3, a_raw, mm);
  } else {
    ain_gemm_body(smem, (int)blockIdx.x - NBIG, d_h2, W3, b3, a_in,
                  mm + 0 * TSTEPS, mm + 1 * TSTEPS);
  }
}

// ---------------- phase 2a: xb + s1 (4-way row split) ----------------
__global__ __launch_bounds__(256) void k_p2a(
    const float* __restrict__ x, const float* __restrict__ state0,
    const float* __restrict__ W_in, const float* __restrict__ W_net) {
  __shared__ float4 st04[125];
  __shared__ float uu[DIMS], xbs[125];
  int bx = blockIdx.x, s = bx >> 2, q = bx & 3;
  int tid = threadIdx.x, w = tid >> 5, lane = tid & 31;
  int n = s & 31, t = s >> 5;
  if (tid < 125) st04[tid] = ((const float4*)(state0 + n * NETS))[tid];
  if (tid < DIMS) uu[tid] = x[n * (DIMS * TSTEPS) + tid * TSTEPS + t];

  float mn_i = __uint_as_float(d_mm[0 * TSTEPS + t]);
  float mx_i = __uint_as_float(d_mm[1 * TSTEPS + t]);
  float mn_n = __uint_as_float(d_mm[2 * TSTEPS + t]);
  float mx_n = __uint_as_float(d_mm[3 * TSTEPS + t]);
  float c1i = __fdividef(100.f, mx_i - mn_i);
  float c0i = -mn_i * c1i - 50.f;
  float c1n = __fdividef(100.f, mx_n - mn_n);
  float c0n = -mn_n * c1n - 50.f;
  int i0 = q * 125;
  __syncthreads();

  if (tid < 125) {
    int i = i0 + tid;
    const float* ar = d_a_in + (size_t)s * AIN_R + i * DIMS;
    const float* wr = W_in + i * DIMS;
    float a = 0.f;
#pragma unroll
    for (int j = 0; j < DIMS; j++) {
      float gate = sigmoid_t(fmaf(ar[j], c1i, c0i));
      a = fmaf(gate * wr[j], uu[j], a);
    }
    xbs[tid] = a;
    d_xb[s * NETS + i] = a;
  }
  __syncthreads();

  for (int r = w; r < 125; r += 8) {
    int i = i0 + r;
    const float4* ar = (const float4*)(d_a_raw + (size_t)s * ANET_R + (size_t)i * NETS);
    const float4* wr = (const float4*)(W_net + (size_t)i * NETS);
    float a = 0.f;
    for (int j4 = lane; j4 < 125; j4 += 32) {
      float4 av = ar[j4], wv = wr[j4], sv = st04[j4];
      a = fmaf(sigmoid_t(fmaf(av.x, c1n, c0n)) * wv.x, sv.x, a);
      a = fmaf(sigmoid_t(fmaf(av.y, c1n, c0n)) * wv.y, sv.y, a);
      a = fmaf(sigmoid_t(fmaf(av.z, c1n, c0n)) * wv.z, sv.z, a);
      a = fmaf(sigmoid_t(fmaf(av.w, c1n, c0n)) * wv.w, sv.w, a);
    }
    a = wredsum(a);
    if (lane == 0) d_s1[s * NETS + i] = fmaxf(a + xbs[r], 0.f);
  }
}

// ---------------- phase 2b: s2 (4-way row split) ----------------
__global__ __launch_bounds__(256) void k_p2b(
    const float* __restrict__ W_net) {
  __shared__ float4 s14[125];
  int bx = blockIdx.x, s = bx >> 2, q = bx & 3;
  int tid = threadIdx.x, w = tid >> 5, lane = tid & 31;
  int t = s >> 5;
  if (tid < 125) s14[tid] = ((const float4*)(d_s1 + s * NETS))[tid];

  float mn_n = __uint_as_float(d_mm[2 * TSTEPS + t]);
  float mx_n = __uint_as_float(d_mm[3 * TSTEPS + t]);
  float c1n = __fdividef(100.f, mx_n - mn_n);
  float c0n = -mn_n * c1n - 50.f;
  int i0 = q * 125;
  __syncthreads();

  for (int r = w; r < 125; r += 8) {
    int i = i0 + r;
    const float4* ar = (const float4*)(d_a_raw + (size_t)s * ANET_R + (size_t)i * NETS);
    const float4* wr = (const float4*)(W_net + (size_t)i * NETS);
    float a = 0.f;
    for (int j4 = lane; j4 < 125; j4 += 32) {
      float4 av = ar[j4], wv = wr[j4], sv = s14[j4];
      a = fmaf(sigmoid_t(fmaf(av.x, c1n, c0n)) * wv.x, sv.x, a);
      a = fmaf(sigmoid_t(fmaf(av.y, c1n, c0n)) * wv.y, sv.y, a);
      a = fmaf(sigmoid_t(fmaf(av.z, c1n, c0n)) * wv.z, sv.z, a);
      a = fmaf(sigmoid_t(fmaf(av.w, c1n, c0n)) * wv.w, sv.w, a);
    }
    a = wredsum(a);
    if (lane == 0) d_s2[s * NETS + i] = fmaxf(a + d_xb[s * NETS + i], 0.f);
  }
}

// ---------------- phase 2c: output projection ----------------
__global__ __launch_bounds__(320) void k_p2c(
    const float* __restrict__ Wo, const float* __restrict__ bo,
    float* __restrict__ out) {
  __shared__ float s2s[NETS];
  int s = blockIdx.x, tid = threadIdx.x, w = tid >> 5, lane = tid & 31;
  int n = s & 31, t = s >> 5;
  for (int i = tid; i < NETS; i += 320) s2s[i] = d_s2[s * NETS + i];
  __syncthreads();
  if (w < DIMS) {
    float a = 0.f;
    for (int i = lane; i < NETS; i += 32) a = fmaf(Wo[w * NETS + i], s2s[i], a);
    a = wredsum(a);
    if (lane == 0) out[n * (DIMS * TSTEPS) + w * TSTEPS + t] = a + bo[w];
  }
}

extern "C" void kernel_launch(void* const* d_in, const int* in_sizes, int n_in,
                              void* d_out, int out_size) {
  const float* x      = (const float*)d_in[0];
  const float* state0 = (const float*)d_in[1];
  const float* W1  = (const float*)d_in[2];  const float* b1  = (const float*)d_in[3];
  const float* W2  = (const float*)d_in[4];  const float* b2  = (const float*)d_in[5];
  const float* W3  = (const float*)d_in[6];  const float* b3  = (const float*)d_in[7];
  const float* Wn1 = (const float*)d_in[8];  const float* bn1 = (const float*)d_in[9];
  const float* Wn2 = (const float*)d_in[10]; const float* bn2 = (const float*)d_in[11];
  const float* Wn3 = (const float*)d_in[12]; const float* bn3 = (const float*)d_in[13];
  const float* W_in  = (const float*)d_in[14];
  const float* W_net = (const float*)d_in[15];
  const float* Wo  = (const float*)d_in[16]; const float* bo  = (const float*)d_in[17];
  float* out = (float*)d_out;

  float *p_ain, *p_araw;
  unsigned* p_mm;
  cudaGetSymbolAddress((void**)&p_ain, d_a_in);
  cudaGetSymbolAddress((void**)&p_araw, d_a_raw);
  cudaGetSymbolAddress((void**)&p_mm, d_mm);

  cudaFuncSetAttribute(k_fused, cudaFuncAttributeMaxDynamicSharedMemorySize, SMEM_BIG);

  k_mlp<<<NSAMP, 256>>>(x, W1, b1, W2, b2, Wn1, bn1, Wn2, bn2);
  k_fused<<<NBIG + NGEMM, 256, SMEM_BIG>>>(Wn3, bn3, W3, b3, p_araw, p_ain, p_mm);
  k_p2a<<<NSAMP * 4, 256>>>(x, state0, W_in, W_net);
  k_p2b<<<NSAMP * 4, 256>>>(W_net);
  k_p2c<<<NSAMP, 320>>>(Wo, bo, out);
}

// round 12
// speedup vs baseline: 1.0364x; 1.0364x over previous
#include <cuda_runtime.h>
#include <cuda_fp16.h>
#include <cstdint>

#define NETS 500
#define DIMS 10
#define NBATCH 32
#define TSTEPS 8
#define NSAMP 256            // s = t*32 + n
#define H1DIM 300
#define AIN_R 5000
#define ANET_R 250000
#define KDIM 500
#define KPAD 512

// ---------------- scratch ----------------
__device__ float d_h2[NSAMP * H1DIM];
__device__ __half d_g2h[NSAMP * KPAD];              // fp16 g2, zero-padded to 512
__device__ float d_a_in[(size_t)NSAMP * AIN_R];
__device__ float d_a_raw[(size_t)NSAMP * ANET_R];   // 256 MB
__device__ unsigned d_mm[4 * TSTEPS];
__device__ float d_xb[NSAMP * NETS];
__device__ float d_s1[NSAMP * NETS];
__device__ float d_s2[NSAMP * NETS];

// ---------------- helpers ----------------
__device__ __forceinline__ uint32_t smem_u32(const void* p) {
  uint32_t a;
  asm("{ .reg .u64 t; cvta.to.shared.u64 t, %1; cvt.u32.u64 %0, t; }" : "=r"(a) : "l"(p));
  return a;
}
__device__ __forceinline__ float wredsum(float v) {
#pragma unroll
  for (int o = 16; o > 0; o >>= 1) v += __shfl_xor_sync(0xffffffffu, v, o);
  return v;
}
__device__ __forceinline__ float sigmoid_t(float z) {
  float t;
  asm("tanh.approx.f32 %0, %1;" : "=f"(t) : "f"(0.5f * z));
  return fmaf(0.5f, t, 0.5f);
}
__device__ __forceinline__ void ldsm4(unsigned* r, uint32_t addr) {
  asm volatile("ldmatrix.sync.aligned.m8n8.x4.shared.b16 {%0,%1,%2,%3}, [%4];"
               : "=r"(r[0]), "=r"(r[1]), "=r"(r[2]), "=r"(r[3]) : "r"(addr));
}
__device__ __forceinline__ void mma_f16(float* c, const unsigned* a, const unsigned* b) {
  asm volatile(
      "mma.sync.aligned.m16n8k16.row.col.f32.f16.f16.f32 "
      "{%0,%1,%2,%3}, {%4,%5,%6,%7}, {%8,%9}, {%0,%1,%2,%3};"
      : "+f"(c[0]), "+f"(c[1]), "+f"(c[2]), "+f"(c[3])
      : "r"(a[0]), "r"(a[1]), "r"(a[2]), "r"(a[3]), "r"(b[0]), "r"(b[1]));
}
__device__ __forceinline__ void cp_async16(uint32_t dst, const void* src) {
  asm volatile("cp.async.ca.shared.global [%0], [%1], 16;" :: "r"(dst), "l"(src));
}
#define CP_COMMIT() asm volatile("cp.async.commit_group;" ::: "memory")
#define CP_WAIT0()  asm volatile("cp.async.wait_group 0;" ::: "memory")

// ---------------- small MLPs (+ d_mm init, g2 -> fp16) ----------------
__global__ __launch_bounds__(256) void k_mlp(
    const float* __restrict__ x,
    const float* __restrict__ W1, const float* __restrict__ b1,
    const float* __restrict__ W2, const float* __restrict__ b2,
    const float* __restrict__ Wn1, const float* __restrict__ bn1,
    const float* __restrict__ Wn2, const float* __restrict__ bn2) {
  __shared__ float uu[DIMS], h1s[H1DIM], g1s[NETS];
  int s = blockIdx.x, tid = threadIdx.x;
  int n = s & 31, t = s >> 5;
  if (s == 0 && tid < TSTEPS) {
    d_mm[0 * TSTEPS + tid] = 0x7F800000u; d_mm[1 * TSTEPS + tid] = 0u;
    d_mm[2 * TSTEPS + tid] = 0x7F800000u; d_mm[3 * TSTEPS + tid] = 0u;
  }
  if (tid < DIMS) uu[tid] = x[n * (DIMS * TSTEPS) + tid * TSTEPS + t];
  if (tid < KPAD - NETS) d_g2h[s * KPAD + NETS + tid] = __ushort_as_half(0);
  __syncthreads();
  for (int o = tid; o < H1DIM; o += 256) {
    float a = b1[o];
#pragma unroll
    for (int k = 0; k < DIMS; k++) a = fmaf(W1[o * DIMS + k], uu[k], a);
    h1s[o] = fmaxf(a, 0.f);
  }
  for (int o = tid; o < NETS; o += 256) {
    float a = bn1[o];
#pragma unroll
    for (int k = 0; k < DIMS; k++) a = fmaf(Wn1[o * DIMS + k], uu[k], a);
    g1s[o] = fmaxf(a, 0.f);
  }
  __syncthreads();
  int w = tid >> 5, lane = tid & 31;
  for (int o = w; o < H1DIM; o += 8) {
    float a = 0.f;
    for (int k = lane; k < H1DIM; k += 32) a = fmaf(W2[o * H1DIM + k], h1s[k], a);
    a = wredsum(a);
    if (lane == 0) d_h2[s * H1DIM + o] = fmaxf(a + b2[o], 0.f);
  }
  for (int o = w; o < NETS; o += 8) {
    float a = 0.f;
    for (int k = lane; k < NETS; k += 32) a = fmaf(Wn2[o * NETS + k], g1s[k], a);
    a = wredsum(a);
    if (lane == 0) d_g2h[s * KPAD + o] = __float2half_rn(fmaxf(a + bn2[o], 0.f));
  }
}

// ================= fused GEMM kernel =================
// Single-pass fp16 GEMM: A = fp16(Wn3), B = fp16(g2), fp32 accum.
// CTA tile M=64 x N=256 (R10 geometry), K-chunk 64 (8 iterations), 2 CTA/SM.
// Fragment-level software pipelining in the MMA loop.
#define A_ROWB 144u
#define A_BLK  (64u * 144u)     // 9216
#define B_BLK  (256u * 144u)    // 36864
#define B_OFF  A_BLK            // 9216
#define BUFSZ  (B_OFF + B_BLK)  // 46080
#define SMEM_BIG (2u * BUFSZ + 64u)  // 92224
#define NCHUNK 8
#define NBIG  ((ANET_R + 63) / 64)   // 3907
#define NGEMM (TSTEPS * ((AIN_R + 127) / 128))  // 320

__device__ __forceinline__ void bigmm_body(
    char* smem, uint32_t sb,
    const float* __restrict__ W, const float* __restrict__ bias,
    float* __restrict__ outp, unsigned* __restrict__ mm) {
  int tid = threadIdx.x, wid = tid >> 5, lane = tid & 31;
  int r0 = blockIdx.x * 64;

  float acc[2][8][4];
#pragma unroll
  for (int a = 0; a < 2; a++)
#pragma unroll
    for (int b = 0; b < 8; b++)
#pragma unroll
      for (int c = 0; c < 4; c++) acc[a][b][c] = 0.f;

  unsigned warpM0 = (wid & 1) * 32, warpN0 = (wid >> 1) * 64;
  unsigned a_off_lane = ((lane & 7) + ((lane >> 3) & 1) * 8) * A_ROWB + (lane >> 4) * 16;
  unsigned b_off_lane = ((lane & 7) + (lane >> 4) * 8) * A_ROWB + ((lane >> 3) & 1) * 16;

  float2 areg[4];
  const unsigned* g2w = (const unsigned*)d_g2h;

  // A: 64 rows x 64 fp32 per chunk = 2048 float2; 8/thread, in 2 halves of 4
  auto ldA = [&](int ch, int half) {
    int k0 = ch * 64;
#pragma unroll
    for (int i = 0; i < 4; i++) {
      int idx = tid + (half * 4 + i) * 256;
      int row = idx >> 5, kp = idx & 31;
      int rg = r0 + row, kg = k0 + 2 * kp;
      bool val = (rg < ANET_R) && (kg + 1 < KDIM);
      areg[i] = val ? *(const float2*)(W + (size_t)rg * KDIM + kg) : make_float2(0.f, 0.f);
    }
  };
  auto stsA = [&](int buf, int half) {
#pragma unroll
    for (int i = 0; i < 4; i++) {
      int idx = tid + (half * 4 + i) * 256;
      int row = idx >> 5, kp = idx & 31;
      __half2 h = __float22half2_rn(areg[i]);
      unsigned off = (unsigned)buf * BUFSZ + (unsigned)row * A_ROWB + (unsigned)kp * 4;
      *(unsigned*)(smem + off) = *(unsigned*)&h;
    }
  };
  // B: 256 rows x 128B per chunk; 8 x 16B per thread
  auto cpB = [&](int ch, int buf) {
    int k0w = ch * 32;
#pragma unroll
    for (int i = 0; i < 8; i++) {
      int idx = tid + i * 256;
      int s = idx >> 3, gran = idx & 7;
      unsigned dst = sb + (unsigned)buf * BUFSZ + B_OFF +
                     (unsigned)s * A_ROWB + (unsigned)gran * 16;
      cp_async16(dst, (const void*)(g2w + (size_t)s * (KPAD / 2) + k0w + gran * 4));
    }
  };
  // MMA over one half-chunk (2 k16 steps) with fragment-level pipelining:
  // B fragments double-buffered; next-ks A fragments prefetched at ntp==3.
  auto mmaHalf = [&](int buf, int kshalf) {
    unsigned base = sb + (unsigned)buf * BUFSZ;
    unsigned baseB = base + B_OFF;
    int ks0 = kshalf * 2;
    unsigned koff0 = (unsigned)ks0 * 32;
    unsigned Aa[2][2][4];   // [kk][mt][4]
    unsigned Bb[2][4];      // pingpong
    ldsm4(Aa[0][0], base + (warpM0 + 0) * A_ROWB + a_off_lane + koff0);
    ldsm4(Aa[0][1], base + (warpM0 + 16) * A_ROWB + a_off_lane + koff0);
    ldsm4(Bb[0], baseB + warpN0 * A_ROWB + b_off_lane + koff0);
#pragma unroll
    for (int kk = 0; kk < 2; kk++) {
      unsigned koff = (unsigned)(ks0 + kk) * 32;
      unsigned koffn = koff + 32;
#pragma unroll
      for (int ntp = 0; ntp < 4; ntp++) {
        int cur = (kk * 4 + ntp) & 1;
        if (ntp < 3) {
          ldsm4(Bb[cur ^ 1],
                baseB + (warpN0 + (ntp + 1) * 16) * A_ROWB + b_off_lane + koff);
        } else if (kk == 0) {
          ldsm4(Aa[1][0], base + (warpM0 + 0) * A_ROWB + a_off_lane + koffn);
          ldsm4(Aa[1][1], base + (warpM0 + 16) * A_ROWB + a_off_lane + koffn);
          ldsm4(Bb[cur ^ 1], baseB + warpN0 * A_ROWB + b_off_lane + koffn);
        }
#pragma unroll
        for (int mt = 0; mt < 2; mt++) {
          mma_f16(acc[mt][2 * ntp], Aa[kk][mt], Bb[cur]);
          mma_f16(acc[mt][2 * ntp + 1], Aa[kk][mt], Bb[cur] + 2);
        }
      }
    }
  };

  // prologue: fill buffer 0
  ldA(0, 0); stsA(0, 0); ldA(0, 1); stsA(0, 1);
  cpB(0, 0); CP_COMMIT();
  CP_WAIT0();
  __syncthreads();

  int buf = 0;
#pragma unroll 1
  for (int ch = 0; ch < NCHUNK; ch++) {
    if (ch < NCHUNK - 1) { ldA(ch + 1, 0); cpB(ch + 1, buf ^ 1); CP_COMMIT(); }
    mmaHalf(buf, 0);
    if (ch < NCHUNK - 1) { stsA(buf ^ 1, 0); ldA(ch + 1, 1); }
    mmaHalf(buf, 1);
    if (ch < NCHUNK - 1) { stsA(buf ^ 1, 1); CP_WAIT0(); }
    __syncthreads();
    buf ^= 1;
  }

  // ---- epilogue: bias + relu + store + per-t min/max ----
  unsigned* smm = (unsigned*)(smem + 2u * BUFSZ);
  if (tid < 8) { smm[tid] = 0x7F800000u; smm[tid + 8] = 0u; }
  __syncthreads();

  float lmn[2], lmx[2];
#pragma unroll
  for (int tg = 0; tg < 2; tg++) { lmn[tg] = __int_as_float(0x7F800000); lmx[tg] = 0.f; }

#pragma unroll
  for (int mt = 0; mt < 2; mt++) {
    int rA = r0 + (int)warpM0 + mt * 16 + (lane >> 2);
    int rB = rA + 8;
    float bA = (rA < ANET_R) ? bias[rA] : 0.f;
    float bB = (rB < ANET_R) ? bias[rB] : 0.f;
#pragma unroll
    for (int nt = 0; nt < 8; nt++) {
      int n0 = (int)warpN0 + nt * 8 + (lane & 3) * 2;
      int tg = nt >> 2;
      float v0 = fmaxf(acc[mt][nt][0] + bA, 0.f);
      float v1 = fmaxf(acc[mt][nt][1] + bA, 0.f);
      float v2 = fmaxf(acc[mt][nt][2] + bB, 0.f);
      float v3 = fmaxf(acc[mt][nt][3] + bB, 0.f);
      if (rA < ANET_R) {
        outp[(size_t)n0 * ANET_R + rA] = v0;
        outp[(size_t)(n0 + 1) * ANET_R + rA] = v1;
        lmn[tg] = fminf(lmn[tg], fminf(v0, v1));
        lmx[tg] = fmaxf(lmx[tg], fmaxf(v0, v1));
      }
      if (rB < ANET_R) {
        outp[(size_t)n0 * ANET_R + rB] = v2;
        outp[(size_t)(n0 + 1) * ANET_R + rB] = v3;
        lmn[tg] = fminf(lmn[tg], fminf(v2, v3));
        lmx[tg] = fmaxf(lmx[tg], fmaxf(v2, v3));
      }
    }
  }
#pragma unroll
  for (int tg = 0; tg < 2; tg++) {
    float mn = lmn[tg], mx = lmx[tg];
#pragma unroll
    for (int o = 16; o > 0; o >>= 1) {
      mn = fminf(mn, __shfl_xor_sync(0xffffffffu, mn, o));
      mx = fmaxf(mx, __shfl_xor_sync(0xffffffffu, mx, o));
    }
    if (lane == 0) {
      int tglob = (int)(warpN0 >> 5) + tg;
      atomicMin(&smm[tglob], __float_as_uint(mn));
      atomicMax(&smm[8 + tglob], __float_as_uint(mx));
    }
  }
  __syncthreads();
  if (tid < 8) {
    atomicMin(&mm[2 * TSTEPS + tid], smm[tid]);
    atomicMax(&mm[3 * TSTEPS + tid], smm[tid + 8]);
  }
}

__device__ __forceinline__ void ain_gemm_body(
    char* smem, int gb,
    const float* __restrict__ G, const float* __restrict__ W,
    const float* __restrict__ bias, float* __restrict__ out,
    unsigned* __restrict__ mmin, unsigned* __restrict__ mmax) {
  const int R = AIN_R, K = H1DIM;
  float (*Wsh)[132] = (float(*)[132])smem;
  float (*Gsh)[34]  = (float(*)[34])(smem + 16 * 132 * 4);
  float* rminmax = (float*)(smem + 16 * 132 * 4 + 16 * 34 * 4);

  int sblk = gb & 7, rblk = gb >> 3, tid = threadIdx.x;
  int rg = tid & 15, sg = tid >> 4;
  int r0 = rblk * 128, s0 = sblk * 32;
  float acc[8][2];
#pragma unroll
  for (int i = 0; i < 8; i++) { acc[i][0] = 0.f; acc[i][1] = 0.f; }
  for (int k0 = 0; k0 < K; k0 += 16) {
#pragma unroll
    for (int i = 0; i < 8; i++) {
      int idx = tid + i * 256, rr = idx >> 4, kk = idx & 15;
      int gr = r0 + rr, gk = k0 + kk;
      Wsh[kk][rr] = (gr < R && gk < K) ? W[(size_t)gr * K + gk] : 0.f;
    }
#pragma unroll
    for (int i = 0; i < 2; i++) {
      int idx = tid + i * 256, ss = idx >> 4, kk = idx & 15;
      int gk = k0 + kk;
      Gsh[kk][ss] = (gk < K) ? G[(size_t)(s0 + ss) * K + gk] : 0.f;
    }
    __syncthreads();
#pragma unroll
    for (int k = 0; k < 16; k++) {
      float4 w0 = *(const float4*)&Wsh[k][rg * 4];
      float4 w1 = *(const float4*)&Wsh[k][64 + rg * 4];
      float g0 = Gsh[k][sg * 2], g1 = Gsh[k][sg * 2 + 1];
      float wv[8] = {w0.x, w0.y, w0.z, w0.w, w1.x, w1.y, w1.z, w1.w};
#pragma unroll
      for (int i = 0; i < 8; i++) {
        acc[i][0] = fmaf(wv[i], g0, acc[i][0]);
        acc[i][1] = fmaf(wv[i], g1, acc[i][1]);
      }
    }
    __syncthreads();
  }
  float tmin = __int_as_float(0x7F800000), tmax = 0.f;
#pragma unroll
  for (int i = 0; i < 8; i++) {
    int r = r0 + ((i < 4) ? (rg * 4 + i) : (64 + rg * 4 + i - 4));
    if (r < R) {
      float b = bias[r];
#pragma unroll
      for (int j = 0; j < 2; j++) {
        float v = fmaxf(acc[i][j] + b, 0.f);
        out[(size_t)(s0 + sg * 2 + j) * R + r] = v;
        tmin = fminf(tmin, v); tmax = fmaxf(tmax, v);
      }
    }
  }
#pragma unroll
  for (int o = 16; o > 0; o >>= 1) {
    tmin = fminf(tmin, __shfl_xor_sync(0xffffffffu, tmin, o));
    tmax = fmaxf(tmax, __shfl_xor_sync(0xffffffffu, tmax, o));
  }
  int w = tid >> 5, lane = tid & 31;
  if (lane == 0) { rminmax[w] = tmin; rminmax[8 + w] = tmax; }
  __syncthreads();
  if (tid == 0) {
#pragma unroll
    for (int i = 1; i < 8; i++) {
      tmin = fminf(tmin, rminmax[i]); tmax = fmaxf(tmax, rminmax[8 + i]);
    }
    atomicMin(&mmin[sblk], __float_as_uint(tmin));
    atomicMax(&mmax[sblk], __float_as_uint(tmax));
  }
}

__global__ __launch_bounds__(256, 2) void k_fused(
    const float* __restrict__ Wn3, const float* __restrict__ bn3,
    const float* __restrict__ W3, const float* __restrict__ b3,
    float* __restrict__ a_raw, float* __restrict__ a_in,
    unsigned* __restrict__ mm) {
  extern __shared__ char smem[];
  uint32_t sb = smem_u32(smem);
  if (blockIdx.x < NBIG) {
    bigmm_body(smem, sb, Wn3, bn3, a_raw, mm);
  } else {
    ain_gemm_body(smem, (int)blockIdx.x - NBIG, d_h2, W3, b3, a_in,
                  mm + 0 * TSTEPS, mm + 1 * TSTEPS);
  }
}

// ---------------- phase 2a: xb + s1 (4-way row split) ----------------
__global__ __launch_bounds__(256) void k_p2a(
    const float* __restrict__ x, const float* __restrict__ state0,
    const float* __restrict__ W_in, const float* __restrict__ W_net) {
  __shared__ float4 st04[125];
  __shared__ float uu[DIMS], xbs[125];
  int bx = blockIdx.x, s = bx >> 2, q = bx & 3;
  int tid = threadIdx.x, w = tid >> 5, lane = tid & 31;
  int n = s & 31, t = s >> 5;
  if (tid < 125) st04[tid] = ((const float4*)(state0 + n * NETS))[tid];
  if (tid < DIMS) uu[tid] = x[n * (DIMS * TSTEPS) + tid * TSTEPS + t];

  float mn_i = __uint_as_float(d_mm[0 * TSTEPS + t]);
  float mx_i = __uint_as_float(d_mm[1 * TSTEPS + t]);
  float mn_n = __uint_as_float(d_mm[2 * TSTEPS + t]);
  float mx_n = __uint_as_float(d_mm[3 * TSTEPS + t]);
  float c1i = __fdividef(100.f, mx_i - mn_i);
  float c0i = -mn_i * c1i - 50.f;
  float c1n = __fdividef(100.f, mx_n - mn_n);
  float c0n = -mn_n * c1n - 50.f;
  int i0 = q * 125;
  __syncthreads();

  if (tid < 125) {
    int i = i0 + tid;
    const float* ar = d_a_in + (size_t)s * AIN_R + i * DIMS;
    const float* wr = W_in + i * DIMS;
    float a = 0.f;
#pragma unroll
    for (int j = 0; j < DIMS; j++) {
      float gate = sigmoid_t(fmaf(ar[j], c1i, c0i));
      a = fmaf(gate * wr[j], uu[j], a);
    }
    xbs[tid] = a;
    d_xb[s * NETS + i] = a;
  }
  __syncthreads();

  for (int r = w; r < 125; r += 8) {
    int i = i0 + r;
    const float4* ar = (const float4*)(d_a_raw + (size_t)s * ANET_R + (size_t)i * NETS);
    const float4* wr = (const float4*)(W_net + (size_t)i * NETS);
    float a = 0.f;
    for (int j4 = lane; j4 < 125; j4 += 32) {
      float4 av = ar[j4], wv = wr[j4], sv = st04[j4];
      a = fmaf(sigmoid_t(fmaf(av.x, c1n, c0n)) * wv.x, sv.x, a);
      a = fmaf(sigmoid_t(fmaf(av.y, c1n, c0n)) * wv.y, sv.y, a);
      a = fmaf(sigmoid_t(fmaf(av.z, c1n, c0n)) * wv.z, sv.z, a);
      a = fmaf(sigmoid_t(fmaf(av.w, c1n, c0n)) * wv.w, sv.w, a);
    }
    a = wredsum(a);
    if (lane == 0) d_s1[s * NETS + i] = fmaxf(a + xbs[r], 0.f);
  }
}

// ---------------- phase 2b: s2 (4-way row split) ----------------
__global__ __launch_bounds__(256) void k_p2b(
    const float* __restrict__ W_net) {
  __shared__ float4 s14[125];
  int bx = blockIdx.x, s = bx >> 2, q = bx & 3;
  int tid = threadIdx.x, w = tid >> 5, lane = tid & 31;
  int t = s >> 5;
  if (tid < 125) s14[tid] = ((const float4*)(d_s1 + s * NETS))[tid];

  float mn_n = __uint_as_float(d_mm[2 * TSTEPS + t]);
  float mx_n = __uint_as_float(d_mm[3 * TSTEPS + t]);
  float c1n = __fdividef(100.f, mx_n - mn_n);
  float c0n = -mn_n * c1n - 50.f;
  int i0 = q * 125;
  __syncthreads();

  for (int r = w; r < 125; r += 8) {
    int i = i0 + r;
    const float4* ar = (const float4*)(d_a_raw + (size_t)s * ANET_R + (size_t)i * NETS);
    const float4* wr = (const float4*)(W_net + (size_t)i * NETS);
    float a = 0.f;
    for (int j4 = lane; j4 < 125; j4 += 32) {
      float4 av = ar[j4], wv = wr[j4], sv = s14[j4];
      a = fmaf(sigmoid_t(fmaf(av.x, c1n, c0n)) * wv.x, sv.x, a);
      a = fmaf(sigmoid_t(fmaf(av.y, c1n, c0n)) * wv.y, sv.y, a);
      a = fmaf(sigmoid_t(fmaf(av.z, c1n, c0n)) * wv.z, sv.z, a);
      a = fmaf(sigmoid_t(fmaf(av.w, c1n, c0n)) * wv.w, sv.w, a);
    }
    a = wredsum(a);
    if (lane == 0) d_s2[s * NETS + i] = fmaxf(a + d_xb[s * NETS + i], 0.f);
  }
}

// ---------------- phase 2c: output projection ----------------
__global__ __launch_bounds__(320) void k_p2c(
    const float* __restrict__ Wo, const float* __restrict__ bo,
    float* __restrict__ out) {
  __shared__ float s2s[NETS];
  int s = blockIdx.x, tid = threadIdx.x, w = tid >> 5, lane = tid & 31;
  int n = s & 31, t = s >> 5;
  for (int i = tid; i < NETS; i += 320) s2s[i] = d_s2[s * NETS + i];
  __syncthreads();
  if (w < DIMS) {
    float a = 0.f;
    for (int i = lane; i < NETS; i += 32) a = fmaf(Wo[w * NETS + i], s2s[i], a);
    a = wredsum(a);
    if (lane == 0) out[n * (DIMS * TSTEPS) + w * TSTEPS + t] = a + bo[w];
  }
}

extern "C" void kernel_launch(void* const* d_in, const int* in_sizes, int n_in,
                              void* d_out, int out_size) {
  const float* x      = (const float*)d_in[0];
  const float* state0 = (const float*)d_in[1];
  const float* W1  = (const float*)d_in[2];  const float* b1  = (const float*)d_in[3];
  const float* W2  = (const float*)d_in[4];  const float* b2  = (const float*)d_in[5];
  const float* W3  = (const float*)d_in[6];  const float* b3  = (const float*)d_in[7];
  const float* Wn1 = (const float*)d_in[8];  const float* bn1 = (const float*)d_in[9];
  const float* Wn2 = (const float*)d_in[10]; const float* bn2 = (const float*)d_in[11];
  const float* Wn3 = (const float*)d_in[12]; const float* bn3 = (const float*)d_in[13];
  const float* W_in  = (const float*)d_in[14];
  const float* W_net = (const float*)d_in[15];
  const float* Wo  = (const float*)d_in[16]; const float* bo  = (const float*)d_in[17];
  float* out = (float*)d_out;

  float *p_ain, *p_araw;
  unsigned* p_mm;
  cudaGetSymbolAddress((void**)&p_ain, d_a_in);
  cudaGetSymbolAddress((void**)&p_araw, d_a_raw);
  cudaGetSymbolAddress((void**)&p_mm, d_mm);

  cudaFuncSetAttribute(k_fused, cudaFuncAttributeMaxDynamicSharedMemorySize, SMEM_BIG);

  k_mlp<<<NSAMP, 256>>>(x, W1, b1, W2, b2, Wn1, bn1, Wn2, bn2);
  k_fused<<<NBIG + NGEMM, 256, SMEM_BIG>>>(Wn3, bn3, W3, b3, p_araw, p_ain, p_mm);
  k_p2a<<<NSAMP * 4, 256>>>(x, state0, W_in, W_net);
  k_p2b<<<NSAMP * 4, 256>>>(W_net);
  k_p2c<<<NSAMP, 320>>>(Wo, bo, out);
}